// round 9
// baseline (speedup 1.0000x reference)
#include <cuda_runtime.h>
#include <math.h>

#define BB 16
#define TT 1024
#define IND 64
#define OUTD 64
#define HHD 512
#define NND 128
#define MMD 40
#define KTOT 616        // IND + HHD + MMD, order [x|h|r]
#define KP4  157        // padded row stride in float4
#define KPAD 628
#define NCTA 128
#define NMEM 16
#define NGEMM 112
#define NTHR 512
#define RWS 20          // gate rows per gemm CTA
#define EPSV 1e-8f
#define RCACHE 80       // projection rows 0..79 cached in smem

// ---------------- persistent global state ----------------
__device__ __align__(16) float g_h[2][BB][HHD];
__device__ __align__(16) float g_r[2][BB][MMD];
__device__ unsigned g_hflags[NGEMM * 32];  // h(t)-ready, one per gemm CTA
__device__ unsigned g_rflags[NMEM * 32];   // r(t)-ready, one per mem CTA
__device__ unsigned g_gen = 0;             // launch generation

static __device__ __forceinline__ unsigned ld_acq(const unsigned* p) {
    unsigned v;
    asm volatile("ld.acquire.gpu.global.u32 %0, [%1];" : "=r"(v) : "l"(p) : "memory");
    return v;
}
static __device__ __forceinline__ void st_rel(unsigned* p, unsigned v) {
    asm volatile("st.release.gpu.global.u32 [%0], %1;" :: "l"(p), "r"(v) : "memory");
}

static __device__ __forceinline__ void wait_hflags(unsigned k) {
    if (threadIdx.x < 32) {
        for (;;) {
            bool ok = true;
            #pragma unroll
            for (int q = 0; q < 4; q++) {
                int f = threadIdx.x + 32 * q;
                if (f < NGEMM)
                    ok &= ((int)(ld_acq(&g_hflags[f * 32]) - k) >= 0);
            }
            if (__all_sync(0xffffffffu, ok)) break;
        }
    }
    __syncthreads();
}

// packed fp32x2 FMA: acc += a * b (lanewise, 2 floats per u64)
#define FMA2(acc, av, bv) \
    asm("fma.rn.f32x2 %0, %1, %2, %0;" : "+l"(acc) : "l"(av), "l"(bv));

struct __align__(16) GemmS {
    alignas(16) float W[RWS * KPAD];       // gate-weight slice [x|h|r]
    alignas(16) float inp[BB * KPAD];      // staged [x|h]
    alignas(16) float red[16 * 320];       // split-K partials (16 chunks)
    float gate[RWS * BB];                  // [lr*16+b]
    float bias[RWS];
    float cst[5 * BB];
};
struct __align__(16) MemS {
    alignas(16) float pw[RCACHE * HHD];    // projection rows 0..79
    alignas(16) float hs[HHD];             // staged h(t)
    alignas(16) float mem[NND * 41];
    float rredA[320];
    float rredB[320];
    float key[MMD];
    float ev[MMD];
    float av[MMD];
    float z[NND];
    float wsm[NND];
    float kb[44];                          // b_k rows 0..39, [40]=b_b
    float eb[MMD];
    float ab[MMD];
    float scal[4];                         // [0]=||key||+eps [1]=beta [2]=s2
};
struct __align__(16) Smem {
    union { GemmS g; MemS m; } u;
    unsigned genv;
};

static __device__ __forceinline__ const float* prow(int r,
    const float* W_k, const float* W_b, const float* W_e, const float* W_a)
{
    if (r < 40)  return W_k + r * HHD;
    if (r == 40) return W_b;
    if (r <= 80) return W_e + (r - 41) * HHD;
    return W_a + (r - 81) * HHD;
}

static __device__ __forceinline__ void proj_epi(MemS& M, int r, float acc) {
    if (r < 40) {
        M.key[r] = tanhf(acc + M.kb[r]);
    } else if (r == 40) {
        float zz = acc + M.kb[40];
        M.scal[1] = fmaxf(zz, 0.f) + log1pf(__expf(-fabsf(zz))) + EPSV;
    } else if (r <= 80) {
        M.ev[r - 41] = 1.f / (1.f + __expf(-(acc + M.eb[r - 41])));
    } else {
        M.av[r - 81] = tanhf(acc + M.ab[r - 81]);
    }
}

#define DOT4(acc, wv, iv) \
    acc += wv.x*iv.x; acc += wv.y*iv.y; acc += wv.z*iv.z; acc += wv.w*iv.w;

// xh-part GEMM (576 dims = f4 0..143).
// warp = K-chunk (16 chunks x 9 f4). lanes 0-15: rows 0-9 for batch=lane;
// lanes 16-31: rows 10-19 for batch=lane-16. W reads broadcast per half-warp.
// Packed f32x2 FMAs halve instruction count.
static __device__ __forceinline__ void gemm_xh(GemmS& G, int tid) {
    const int kc = tid >> 5;
    const int lane = tid & 31;
    const int half = lane >> 4, b = lane & 15;
    const int rowbase = half * 10;
    const int koff = kc * 9;
    const ulonglong2* W2 = reinterpret_cast<const ulonglong2*>(G.W);
    const ulonglong2* I2 = reinterpret_cast<const ulonglong2*>(G.inp);
    unsigned long long acc[10];
    #pragma unroll
    for (int i = 0; i < 10; i++) acc[i] = 0ull;
    #pragma unroll
    for (int q = 0; q < 9; q++) {
        ulonglong2 iv = I2[b * KP4 + koff + q];
        #pragma unroll
        for (int i = 0; i < 10; i++) {
            ulonglong2 wv = W2[(rowbase + i) * KP4 + koff + q];
            FMA2(acc[i], wv.x, iv.x)
            FMA2(acc[i], wv.y, iv.y)
        }
    }
    #pragma unroll
    for (int i = 0; i < 10; i++) {
        float lo, hi;
        asm("mov.b64 {%0, %1}, %2;" : "=f"(lo), "=f"(hi) : "l"(acc[i]));
        G.red[kc * 320 + (rowbase + i) * 16 + b] = lo + hi;
    }
}

__global__ void __launch_bounds__(NTHR, 1) ntm_kernel(
    const float* __restrict__ x,    const float* __restrict__ h0,
    const float* __restrict__ c0,   const float* __restrict__ mem0,
    const float* __restrict__ r0_,  const float* __restrict__ W_ih,
    const float* __restrict__ b_ih, const float* __restrict__ W_hh,
    const float* __restrict__ b_hh, const float* __restrict__ W_fc,
    const float* __restrict__ b_fc, const float* __restrict__ W_e,
    const float* __restrict__ b_e,  const float* __restrict__ W_a,
    const float* __restrict__ b_a,  const float* __restrict__ W_k,
    const float* __restrict__ b_k,  const float* __restrict__ W_b,
    const float* __restrict__ b_b,  float* __restrict__ out)
{
    extern __shared__ unsigned char smem_raw[];
    Smem& s = *reinterpret_cast<Smem*>(smem_raw);
    const int cta = blockIdx.x;
    const int tid = threadIdx.x;
    const int lane = tid & 31, wrp = tid >> 5;

    float* out_O = out;
    float* out_h = out + (size_t)BB * TT * OUTD;
    float* out_c = out_h + BB * HHD;

    if (tid == 0) s.genv = ld_acq(&g_gen);

    const bool is_mem = (cta < NMEM);
    const int gi = cta - NMEM;
    const int cnt   = (gi < 64) ? 5 : 4;
    const int hbase = (gi < 64) ? gi * 5 : 320 + (gi - 64) * 4;

    // ---------------- init ----------------
    if (!is_mem) {
        GemmS& G = s.u.g;
        for (int idx = tid; idx < RWS * KPAD; idx += NTHR) {
            int lr = idx / KPAD, k = idx - lr * KPAD;
            int g = lr & 3, hl = lr >> 2;
            float v = 0.f;
            if (hl < cnt) {
                int gr = g * HHD + hbase + hl;
                if (k < IND)             v = W_ih[gr * (IND + MMD) + k];
                else if (k < IND + HHD)  v = W_hh[gr * HHD + (k - IND)];
                else if (k < KTOT)       v = W_ih[gr * (IND + MMD) + IND + (k - IND - HHD)];
            }
            G.W[idx] = v;
        }
        if (tid < RWS) {
            int g = tid & 3, hl = tid >> 2;
            G.bias[tid] = (hl < cnt)
                ? (b_ih[g * HHD + hbase + hl] + b_hh[g * HHD + hbase + hl]) : 0.f;
        }
        if (tid < 5 * BB) {
            int b = tid / 5, hl = tid - b * 5;
            G.cst[hl * BB + b] = (hl < cnt) ? c0[b * HHD + hbase + hl] : 0.f;
        }
        for (int idx = tid; idx < BB * KPAD; idx += NTHR) {
            int b = idx / KPAD, k = idx - b * KPAD;
            float v = 0.f;
            if (k < IND)             v = x[(b * TT) * IND + k];
            else if (k < IND + HHD)  v = h0[b * HHD + (k - IND)];
            G.inp[idx] = v;
        }
        __syncthreads();
        gemm_xh(G, tid);                 // xh partials for t = 0
    } else {
        MemS& M = s.u.m;
        for (int idx = tid; idx < RCACHE * HHD; idx += NTHR) {
            int r = idx >> 9, k = idx & (HHD - 1);
            M.pw[idx] = prow(r, W_k, W_b, W_e, W_a)[k];
        }
        for (int idx = tid; idx < NND * MMD; idx += NTHR) {
            int n = idx / MMD, m = idx - n * MMD;
            M.mem[n * 41 + m] = mem0[cta * NND * MMD + idx];
        }
        if (tid < 40) {
            M.kb[tid] = b_k[tid];
            M.eb[tid] = b_e[tid];
            M.ab[tid] = b_a[tid];
        }
        if (tid == 40) M.kb[40] = b_b[0];
        if (tid < MMD) g_r[1][cta][tid] = r0_[cta * MMD + tid];
    }
    __syncthreads();
    const unsigned gen = s.genv;
    const unsigned hb0 = gen * (unsigned)TT;
    const unsigned rb0 = gen * (unsigned)TT;
    if (is_mem && tid == 0) {
        __threadfence();
        st_rel(&g_rflags[cta * 32], rb0);      // r(-1) ready
    }

    if (is_mem) {
        // =================== memory CTA loop ===================
        MemS& M = s.u.m;
        const int b = cta;
        for (int t = 0; t < TT - 1; t++) {
            const int hp = t & 1;
            wait_hflags(hb0 + (unsigned)(t + 1));
            if (tid < 128) {
                reinterpret_cast<float4*>(M.hs)[tid] = __ldcg(
                    reinterpret_cast<const float4*>(&g_h[hp][b][0]) + tid);
            }
            __syncthreads();
            const float4* hs4 = reinterpret_cast<const float4*>(M.hs);
            float4 hv0 = hs4[lane];
            float4 hv1 = hs4[lane + 32];
            float4 hv2 = hs4[lane + 64];
            float4 hv3 = hs4[lane + 96];
            // ---- Phase K: key + beta rows (0..40, all smem) ----
            #pragma unroll
            for (int j = 0; j < 3; j++) {
                int r = wrp + 16 * j;
                if (r <= 40) {
                    const float4* w4 =
                        reinterpret_cast<const float4*>(&M.pw[r * HHD]);
                    float4 a0 = w4[lane],      a1 = w4[lane + 32];
                    float4 a2 = w4[lane + 64], a3 = w4[lane + 96];
                    float acc = 0.f;
                    DOT4(acc, a0, hv0) DOT4(acc, a1, hv1)
                    DOT4(acc, a2, hv2) DOT4(acc, a3, hv3)
                    #pragma unroll
                    for (int off = 16; off; off >>= 1)
                        acc += __shfl_xor_sync(0xffffffffu, acc, off);
                    if (lane == 0) proj_epi(M, r, acc);
                }
            }
            __syncthreads();
            // ---- Phase E1: sim + keynorm || L2 rows (80..120) ----
            if (wrp < 4) {
                const float* mr = &M.mem[tid * 41];
                float dot = 0.f, nrm = 0.f;
                #pragma unroll
                for (int m = 0; m < MMD; m++) {
                    float mv = mr[m];
                    dot += mv * M.key[m];
                    nrm += mv * mv;
                }
                M.z[tid] = dot / (sqrtf(nrm) + EPSV);
            } else if (wrp == 4) {
                float v = 0.f;
                if (lane < MMD)      { float kv = M.key[lane];      v  = kv * kv; }
                if (lane + 32 < MMD) { float kv = M.key[lane + 32]; v += kv * kv; }
                #pragma unroll
                for (int off = 16; off; off >>= 1)
                    v += __shfl_xor_sync(0xffffffffu, v, off);
                if (lane == 0) M.scal[0] = sqrtf(v) + EPSV;
            } else {
                int i = wrp - 5;
                int rows[4]; const float4* wp[4]; int nv = 0;
                #pragma unroll
                for (int j = 0; j < 4; j++) {
                    int r = 80 + i + 11 * j;
                    if (r <= 120) {
                        rows[nv] = r;
                        wp[nv] = reinterpret_cast<const float4*>(
                            prow(r, W_k, W_b, W_e, W_a));
                        nv++;
                    }
                }
                float4 c0v, c1v, c2v, c3v;
                if (nv > 0) {
                    c0v = __ldg(wp[0] + lane);      c1v = __ldg(wp[0] + lane + 32);
                    c2v = __ldg(wp[0] + lane + 64); c3v = __ldg(wp[0] + lane + 96);
                }
                for (int q = 0; q < nv; q++) {
                    float4 n0, n1, n2, n3;
                    if (q + 1 < nv) {
                        n0 = __ldg(wp[q+1] + lane);      n1 = __ldg(wp[q+1] + lane + 32);
                        n2 = __ldg(wp[q+1] + lane + 64); n3 = __ldg(wp[q+1] + lane + 96);
                    }
                    float acc = 0.f;
                    DOT4(acc, c0v, hv0) DOT4(acc, c1v, hv1)
                    DOT4(acc, c2v, hv2) DOT4(acc, c3v, hv3)
                    #pragma unroll
                    for (int off = 16; off; off >>= 1)
                        acc += __shfl_xor_sync(0xffffffffu, acc, off);
                    if (lane == 0) proj_epi(M, rows[q], acc);
                    c0v = n0; c1v = n1; c2v = n2; c3v = n3;
                }
            }
            __syncthreads();
            // ---- Phase E2: softmax || smem e-rows (41..79) ----
            if (wrp == 0) {
                float bscale = M.scal[1] / M.scal[0];
                float z0 = M.z[lane]      * bscale;
                float z1 = M.z[lane + 32] * bscale;
                float z2 = M.z[lane + 64] * bscale;
                float z3 = M.z[lane + 96] * bscale;
                float mx = fmaxf(fmaxf(z0, z1), fmaxf(z2, z3));
                #pragma unroll
                for (int off = 16; off; off >>= 1)
                    mx = fmaxf(mx, __shfl_xor_sync(0xffffffffu, mx, off));
                float e0 = __expf(z0 - mx), e1 = __expf(z1 - mx);
                float e2 = __expf(z2 - mx), e3 = __expf(z3 - mx);
                float sv = e0 + e1 + e2 + e3;
                #pragma unroll
                for (int off = 16; off; off >>= 1)
                    sv += __shfl_xor_sync(0xffffffffu, sv, off);
                float inv = 1.f / sv;
                float w0 = e0 * inv, w1 = e1 * inv, w2 = e2 * inv, w3 = e3 * inv;
                M.wsm[lane]      = w0;
                M.wsm[lane + 32] = w1;
                M.wsm[lane + 64] = w2;
                M.wsm[lane + 96] = w3;
                float sq = w0*w0 + w1*w1 + w2*w2 + w3*w3;
                #pragma unroll
                for (int off = 16; off; off >>= 1)
                    sq += __shfl_xor_sync(0xffffffffu, sq, off);
                if (lane == 0) M.scal[2] = sq;
            } else {
                int i = wrp - 1;
                #pragma unroll
                for (int j = 0; j < 3; j++) {
                    int r = 41 + i + 15 * j;
                    if (r <= 79) {
                        const float4* w4 =
                            reinterpret_cast<const float4*>(&M.pw[r * HHD]);
                        float4 a0 = w4[lane],      a1 = w4[lane + 32];
                        float4 a2 = w4[lane + 64], a3 = w4[lane + 96];
                        float acc = 0.f;
                        DOT4(acc, a0, hv0) DOT4(acc, a1, hv1)
                        DOT4(acc, a2, hv2) DOT4(acc, a3, hv3)
                        #pragma unroll
                        for (int off = 16; off; off >>= 1)
                            acc += __shfl_xor_sync(0xffffffffu, acc, off);
                        if (lane == 0) proj_epi(M, r, acc);
                    }
                }
            }
            __syncthreads();
            // ---- A/B partials over OLD memory ----
            if (tid < 320) {
                int m = tid >> 3, p = tid & 7;
                float A = 0.f, Bv = 0.f;
                #pragma unroll
                for (int n = p * 16; n < p * 16 + 16; n++) {
                    float w = M.wsm[n];
                    float mv = M.mem[n * 41 + m];
                    A  += w * mv;
                    Bv += w * w * mv;
                }
                M.rredA[tid] = A;
                M.rredB[tid] = Bv;
            }
            __syncthreads();
            // ---- r = A - e.B + s2*a  (over old memory; post flag early) ----
            if (tid < MMD) {
                float A = 0.f, Bv = 0.f;
                #pragma unroll
                for (int p = 0; p < 8; p++) {
                    A  += M.rredA[tid * 8 + p];
                    Bv += M.rredB[tid * 8 + p];
                }
                g_r[hp][b][tid] = A - M.ev[tid] * Bv + M.scal[2] * M.av[tid];
            }
            __syncthreads();
            if (tid == 0) {
                __threadfence();
                st_rel(&g_rflags[cta * 32], rb0 + (unsigned)(t + 1));
            }
            // ---- memory erase/add (off critical path) ----
            if (tid < NND) {
                float wv = M.wsm[tid];
                float* mr = &M.mem[tid * 41];
                #pragma unroll
                for (int m = 0; m < MMD; m++)
                    mr[m] = mr[m] * (1.f - wv * M.ev[m]) + wv * M.av[m];
            }
        }
    } else {
        // =================== gemm CTA loop ===================
        GemmS& G = s.u.g;
        for (int t = 0; t < TT; t++) {
            const int hp = t & 1;
            // ---- part 1: wait r(t-1); fused reduce (16 chunks + bias + r-dot) ----
            if (wrp == 0) {
                unsigned tgt = rb0 + (unsigned)t;
                for (;;) {
                    bool ok = true;
                    if (lane < NMEM)
                        ok = ((int)(ld_acq(&g_rflags[lane * 32]) - tgt) >= 0);
                    if (__all_sync(0xffffffffu, ok)) break;
                }
            }
            __syncthreads();
            if (tid < 320) {
                int lr = tid >> 4, b = tid & 15;
                const float4* R4 =
                    reinterpret_cast<const float4*>(&g_r[hp ^ 1][b][0]);
                float4 rv[10];
                #pragma unroll
                for (int q = 0; q < 10; q++) rv[q] = __ldcg(R4 + q);
                float v = G.bias[lr];
                #pragma unroll
                for (int kc2 = 0; kc2 < 16; kc2++) v += G.red[kc2 * 320 + tid];
                const float4* w4 =
                    reinterpret_cast<const float4*>(G.W) + lr * KP4 + 144;
                #pragma unroll
                for (int q = 0; q < 10; q++) {
                    float4 wv = w4[q];
                    DOT4(v, wv, rv[q])
                }
                G.gate[tid] = v;
            }
            __syncthreads();
            if (tid < 5 * BB) {        // LSTM pointwise -> h(t)
                int b = tid / 5, hl = tid - b * 5;
                if (hl < cnt) {
                    float gv_i = G.gate[(4 * hl + 0) * 16 + b];
                    float gv_f = G.gate[(4 * hl + 1) * 16 + b];
                    float gv_g = G.gate[(4 * hl + 2) * 16 + b];
                    float gv_o = G.gate[(4 * hl + 3) * 16 + b];
                    float iv = 1.f / (1.f + __expf(-gv_i));
                    float fv = 1.f / (1.f + __expf(-gv_f));
                    float gv = tanhf(gv_g);
                    float ov = 1.f / (1.f + __expf(-gv_o));
                    float cn = fv * G.cst[hl * BB + b] + iv * gv;
                    float hn = ov * tanhf(cn);
                    G.cst[hl * BB + b] = cn;
                    g_h[hp][b][hbase + hl] = hn;
                    if (t == TT - 1) {
                        out_h[b * HHD + hbase + hl] = hn;
                        out_c[b * HHD + hbase + hl] = cn;
                    }
                }
            }
            __syncthreads();
            if (tid == 0) {
                __threadfence();
                st_rel(&g_hflags[gi * 32], hb0 + (unsigned)(t + 1));
            }
            // ---- window B: prestage, fc(t), xh-gemm(t+1) ----
            wait_hflags(hb0 + (unsigned)(t + 1));
            for (int idx = tid; idx < BB * 144; idx += NTHR) {
                int b = idx / 144, q = idx - b * 144;
                float4 v;
                if (q < 16) {
                    v = (t + 1 < TT)
                        ? __ldg(reinterpret_cast<const float4*>(
                              &x[(b * TT + t + 1) * IND]) + q)
                        : make_float4(0.f, 0.f, 0.f, 0.f);
                } else {
                    v = __ldcg(reinterpret_cast<const float4*>(&g_h[hp][b][0])
                               + (q - 16));
                }
                reinterpret_cast<float4*>(G.inp)[b * KP4 + q] = v;
            }
            __syncthreads();
            {   // fc(t) from staged h
                int grp = tid >> 4, l16 = tid & 15;
                int d = gi + NGEMM * grp;
                bool valid = (d < 1024);
                int d2 = valid ? d : 0;
                int b = d2 >> 6, row = d2 & 63;
                const float4* w4 =
                    reinterpret_cast<const float4*>(W_fc + row * HHD);
                const float4* h4 =
                    reinterpret_cast<const float4*>(G.inp) + b * KP4 + 16;
                float acc = 0.f;
                #pragma unroll
                for (int q = 0; q < 8; q++) {
                    float4 wv = __ldg(w4 + l16 + 16 * q);
                    float4 hv = h4[l16 + 16 * q];
                    DOT4(acc, wv, hv)
                }
                #pragma unroll
                for (int off = 8; off; off >>= 1)
                    acc += __shfl_xor_sync(0xffffffffu, acc, off);
                if (valid && l16 == 0)
                    out_O[(b * TT + t) * OUTD + row] = tanhf(acc + b_fc[row]);
            }
            if (t + 1 < TT) gemm_xh(G, tid);
        }
        if (cta == NCTA - 1 && tid == 0) {
            st_rel(&g_gen, gen + 1);
        }
    }
}

extern "C" void kernel_launch(void* const* d_in, const int* in_sizes, int n_in,
                              void* d_out, int out_size) {
    (void)in_sizes; (void)n_in; (void)out_size;
    cudaFuncSetAttribute(ntm_kernel,
                         cudaFuncAttributeMaxDynamicSharedMemorySize,
                         (int)sizeof(Smem));
    ntm_kernel<<<NCTA, NTHR, sizeof(Smem)>>>(
        (const float*)d_in[0],  (const float*)d_in[1],  (const float*)d_in[2],
        (const float*)d_in[3],  (const float*)d_in[4],  (const float*)d_in[5],
        (const float*)d_in[6],  (const float*)d_in[7],  (const float*)d_in[8],
        (const float*)d_in[9],  (const float*)d_in[10], (const float*)d_in[11],
        (const float*)d_in[12], (const float*)d_in[13], (const float*)d_in[14],
        (const float*)d_in[15], (const float*)d_in[16], (const float*)d_in[17],
        (const float*)d_in[18], (float*)d_out);
}

// round 10
// speedup vs baseline: 1.8192x; 1.8192x over previous
#include <cuda_runtime.h>
#include <math.h>

#define BB 16
#define TT 1024
#define IND 64
#define OUTD 64
#define HHD 512
#define NND 128
#define MMD 40
#define KTOT 616        // IND + HHD + MMD, order [x|h|r]
#define KP4  157        // padded row stride in float4
#define KPAD 628
#define NCTA 128
#define NMEM 16
#define NGEMM 112
#define NTHR 512
#define RWS 20          // gate rows per gemm CTA
#define EPSV 1e-8f
#define RCACHE 80       // projection rows 0..79 cached in smem

// ---------------- persistent global state ----------------
__device__ __align__(16) float g_h[2][BB][HHD];
__device__ __align__(16) float g_r[2][BB][MMD];
__device__ unsigned g_hflags[NGEMM * 32];  // h(t)-ready, one per gemm CTA
__device__ unsigned g_rflags[NMEM * 32];   // r(t)-ready, one per mem CTA
__device__ unsigned g_gen = 0;             // launch generation

static __device__ __forceinline__ unsigned ld_acq(const unsigned* p) {
    unsigned v;
    asm volatile("ld.acquire.gpu.global.u32 %0, [%1];" : "=r"(v) : "l"(p) : "memory");
    return v;
}
static __device__ __forceinline__ void st_rel(unsigned* p, unsigned v) {
    asm volatile("st.release.gpu.global.u32 [%0], %1;" :: "l"(p), "r"(v) : "memory");
}

static __device__ __forceinline__ void wait_hflags(unsigned k) {
    if (threadIdx.x < 32) {
        for (;;) {
            bool ok = true;
            #pragma unroll
            for (int q = 0; q < 4; q++) {
                int f = threadIdx.x + 32 * q;
                if (f < NGEMM)
                    ok &= ((int)(ld_acq(&g_hflags[f * 32]) - k) >= 0);
            }
            if (__all_sync(0xffffffffu, ok)) break;
        }
    }
    __syncthreads();
}

struct __align__(16) GemmS {
    alignas(16) float W[RWS * KPAD];       // gate-weight slice [x|h|r]
    alignas(16) float inp[BB * KPAD];      // staged [x|h|r]
    alignas(16) float red[32 * 16 * RWS];  // split-K partials
    float gate[RWS * BB];
    float bias[RWS];
    float cst[5 * BB];
};
struct __align__(16) MemS {
    alignas(16) float pw[RCACHE * HHD];    // projection rows 0..79
    alignas(16) float hs[HHD];             // staged h(t)
    alignas(16) float mem[NND * 41];
    float rredA[320];
    float rredB[320];
    float key[MMD];
    float ev[MMD];
    float av[MMD];
    float z[NND];
    float wsm[NND];
    float kb[44];                          // b_k rows 0..39, [40]=b_b
    float eb[MMD];
    float ab[MMD];
    float scal[4];                         // [0]=||key||+eps [1]=beta [2]=s2
};
struct __align__(16) Smem {
    union { GemmS g; MemS m; } u;
    unsigned genv;
};

static __device__ __forceinline__ const float* prow(int r,
    const float* W_k, const float* W_b, const float* W_e, const float* W_a)
{
    if (r < 40)  return W_k + r * HHD;
    if (r == 40) return W_b;
    if (r <= 80) return W_e + (r - 41) * HHD;
    return W_a + (r - 81) * HHD;
}

static __device__ __forceinline__ void proj_epi(MemS& M, int r, float acc) {
    if (r < 40) {
        M.key[r] = tanhf(acc + M.kb[r]);
    } else if (r == 40) {
        float zz = acc + M.kb[40];
        M.scal[1] = fmaxf(zz, 0.f) + log1pf(__expf(-fabsf(zz))) + EPSV;
    } else if (r <= 80) {
        M.ev[r - 41] = 1.f / (1.f + __expf(-(acc + M.eb[r - 41])));
    } else {
        M.av[r - 81] = tanhf(acc + M.ab[r - 81]);
    }
}

#define DOT4(acc, wv, iv) \
    acc += wv.x*iv.x; acc += wv.y*iv.y; acc += wv.z*iv.z; acc += wv.w*iv.w;

// xh-part GEMM (576 dims = f4 0..143), conflict-free interleaved mapping (R7).
static __device__ __forceinline__ void gemm_xh(GemmS& G, int tid) {
    const int kc = tid >> 4, tile = tid & 15;
    const int rg = tile & 3, bg = tile >> 2;
    const int koff = (kc < 16) ? kc * 5 : 80 + (kc - 16) * 4;
    const int klen = (kc < 16) ? 5 : 4;
    const float4* W4 = reinterpret_cast<const float4*>(G.W);
    const float4* I4 = reinterpret_cast<const float4*>(G.inp);
    float a[20];
    #pragma unroll
    for (int q = 0; q < 20; q++) a[q] = 0.f;
    #pragma unroll 5
    for (int q = 0; q < klen; q++) {
        float4 wv[5], iv[4];
        #pragma unroll
        for (int i = 0; i < 5; i++) wv[i] = W4[(rg + 4 * i) * KP4 + koff + q];
        #pragma unroll
        for (int j = 0; j < 4; j++) iv[j] = I4[(bg + 4 * j) * KP4 + koff + q];
        #pragma unroll
        for (int i = 0; i < 5; i++) {
            #pragma unroll
            for (int j = 0; j < 4; j++) { DOT4(a[i * 4 + j], wv[i], iv[j]) }
        }
    }
    float* rb = &G.red[(kc * 16 + tile) * RWS];
    #pragma unroll
    for (int q = 0; q < 20; q++) rb[q] = a[q];
}

__global__ void __launch_bounds__(NTHR, 1) ntm_kernel(
    const float* __restrict__ x,    const float* __restrict__ h0,
    const float* __restrict__ c0,   const float* __restrict__ mem0,
    const float* __restrict__ r0_,  const float* __restrict__ W_ih,
    const float* __restrict__ b_ih, const float* __restrict__ W_hh,
    const float* __restrict__ b_hh, const float* __restrict__ W_fc,
    const float* __restrict__ b_fc, const float* __restrict__ W_e,
    const float* __restrict__ b_e,  const float* __restrict__ W_a,
    const float* __restrict__ b_a,  const float* __restrict__ W_k,
    const float* __restrict__ b_k,  const float* __restrict__ W_b,
    const float* __restrict__ b_b,  float* __restrict__ out)
{
    extern __shared__ unsigned char smem_raw[];
    Smem& s = *reinterpret_cast<Smem*>(smem_raw);
    const int cta = blockIdx.x;
    const int tid = threadIdx.x;
    const int lane = tid & 31, wrp = tid >> 5;

    float* out_O = out;
    float* out_h = out + (size_t)BB * TT * OUTD;
    float* out_c = out_h + BB * HHD;

    if (tid == 0) s.genv = ld_acq(&g_gen);

    const bool is_mem = (cta < NMEM);
    const int gi = cta - NMEM;
    const int cnt   = (gi < 64) ? 5 : 4;
    const int hbase = (gi < 64) ? gi * 5 : 320 + (gi - 64) * 4;

    // ---------------- init (gemm side identical to R7) ----------------
    if (!is_mem) {
        GemmS& G = s.u.g;
        for (int idx = tid; idx < RWS * KPAD; idx += NTHR) {
            int lr = idx / KPAD, k = idx - lr * KPAD;
            int g = lr & 3, hl = lr >> 2;
            float v = 0.f;
            if (hl < cnt) {
                int gr = g * HHD + hbase + hl;
                if (k < IND)             v = W_ih[gr * (IND + MMD) + k];
                else if (k < IND + HHD)  v = W_hh[gr * HHD + (k - IND)];
                else if (k < KTOT)       v = W_ih[gr * (IND + MMD) + IND + (k - IND - HHD)];
            }
            G.W[idx] = v;
        }
        if (tid < RWS) {
            int g = tid & 3, hl = tid >> 2;
            G.bias[tid] = (hl < cnt)
                ? (b_ih[g * HHD + hbase + hl] + b_hh[g * HHD + hbase + hl]) : 0.f;
        }
        if (tid < 5 * BB) {
            int b = tid / 5, hl = tid - b * 5;
            G.cst[hl * BB + b] = (hl < cnt) ? c0[b * HHD + hbase + hl] : 0.f;
        }
        for (int idx = tid; idx < BB * KPAD; idx += NTHR) {
            int b = idx / KPAD, k = idx - b * KPAD;
            float v = 0.f;
            if (k < IND)             v = x[(b * TT) * IND + k];
            else if (k < IND + HHD)  v = h0[b * HHD + (k - IND)];
            else if (k < KTOT)       v = r0_[b * MMD + (k - IND - HHD)];
            G.inp[idx] = v;
        }
        __syncthreads();
        gemm_xh(G, tid);               // xh partials for t = 0
    } else {
        MemS& M = s.u.m;
        for (int idx = tid; idx < RCACHE * HHD; idx += NTHR) {
            int r = idx >> 9, k = idx & (HHD - 1);
            M.pw[idx] = prow(r, W_k, W_b, W_e, W_a)[k];
        }
        for (int idx = tid; idx < NND * MMD; idx += NTHR) {
            int n = idx / MMD, m = idx - n * MMD;
            M.mem[n * 41 + m] = mem0[cta * NND * MMD + idx];
        }
        if (tid < 40) {
            M.kb[tid] = b_k[tid];
            M.eb[tid] = b_e[tid];
            M.ab[tid] = b_a[tid];
        }
        if (tid == 40) M.kb[40] = b_b[0];
    }
    __syncthreads();
    const unsigned gen = s.genv;
    const unsigned hb0 = gen * (unsigned)TT;        // h-flag base this launch
    const unsigned rb0 = gen * (unsigned)(TT - 1);  // r-flag base this launch

    if (is_mem) {
        // =================== memory CTA loop (phased, R8-proven) ===================
        MemS& M = s.u.m;
        const int b = cta;
        for (int t = 0; t < TT - 1; t++) {
            const int hp = t & 1;
            wait_hflags(hb0 + (unsigned)(t + 1));
            // stage h(t) into smem once
            if (tid < 128) {
                reinterpret_cast<float4*>(M.hs)[tid] = __ldcg(
                    reinterpret_cast<const float4*>(&g_h[hp][b][0]) + tid);
            }
            __syncthreads();
            const float4* hs4 = reinterpret_cast<const float4*>(M.hs);
            float4 hv0 = hs4[lane];
            float4 hv1 = hs4[lane + 32];
            float4 hv2 = hs4[lane + 64];
            float4 hv3 = hs4[lane + 96];
            // ---- Phase K: key + beta rows (0..40, all smem) ----
            #pragma unroll
            for (int j = 0; j < 3; j++) {
                int r = wrp + 16 * j;
                if (r <= 40) {
                    const float4* w4 =
                        reinterpret_cast<const float4*>(&M.pw[r * HHD]);
                    float4 a0 = w4[lane],      a1 = w4[lane + 32];
                    float4 a2 = w4[lane + 64], a3 = w4[lane + 96];
                    float acc = 0.f;
                    DOT4(acc, a0, hv0) DOT4(acc, a1, hv1)
                    DOT4(acc, a2, hv2) DOT4(acc, a3, hv3)
                    #pragma unroll
                    for (int off = 16; off; off >>= 1)
                        acc += __shfl_xor_sync(0xffffffffu, acc, off);
                    if (lane == 0) proj_epi(M, r, acc);
                }
            }
            __syncthreads();
            // ---- Phase E1: sim + keynorm || L2 rows (80..120) ----
            if (wrp < 4) {
                const float* mr = &M.mem[tid * 41];
                float dot = 0.f, nrm = 0.f;
                #pragma unroll
                for (int m = 0; m < MMD; m++) {
                    float mv = mr[m];
                    dot += mv * M.key[m];
                    nrm += mv * mv;
                }
                M.z[tid] = dot / (sqrtf(nrm) + EPSV);
            } else if (wrp == 4) {
                float v = 0.f;
                if (lane < MMD)      { float kv = M.key[lane];      v  = kv * kv; }
                if (lane + 32 < MMD) { float kv = M.key[lane + 32]; v += kv * kv; }
                #pragma unroll
                for (int off = 16; off; off >>= 1)
                    v += __shfl_xor_sync(0xffffffffu, v, off);
                if (lane == 0) M.scal[0] = sqrtf(v) + EPSV;
            } else {
                int i = wrp - 5;
                int rows[4]; const float4* wp[4]; int nv = 0;
                #pragma unroll
                for (int j = 0; j < 4; j++) {
                    int r = 80 + i + 11 * j;
                    if (r <= 120) {
                        rows[nv] = r;
                        wp[nv] = reinterpret_cast<const float4*>(
                            prow(r, W_k, W_b, W_e, W_a));
                        nv++;
                    }
                }
                float4 c0v, c1v, c2v, c3v;
                if (nv > 0) {
                    c0v = __ldg(wp[0] + lane);      c1v = __ldg(wp[0] + lane + 32);
                    c2v = __ldg(wp[0] + lane + 64); c3v = __ldg(wp[0] + lane + 96);
                }
                for (int q = 0; q < nv; q++) {
                    float4 n0, n1, n2, n3;
                    if (q + 1 < nv) {
                        n0 = __ldg(wp[q+1] + lane);      n1 = __ldg(wp[q+1] + lane + 32);
                        n2 = __ldg(wp[q+1] + lane + 64); n3 = __ldg(wp[q+1] + lane + 96);
                    }
                    float acc = 0.f;
                    DOT4(acc, c0v, hv0) DOT4(acc, c1v, hv1)
                    DOT4(acc, c2v, hv2) DOT4(acc, c3v, hv3)
                    #pragma unroll
                    for (int off = 16; off; off >>= 1)
                        acc += __shfl_xor_sync(0xffffffffu, acc, off);
                    if (lane == 0) proj_epi(M, rows[q], acc);
                    c0v = n0; c1v = n1; c2v = n2; c3v = n3;
                }
            }
            __syncthreads();
            // ---- Phase E2: softmax || smem e-rows (41..79) ----
            if (wrp == 0) {
                float bscale = M.scal[1] / M.scal[0];
                float z0 = M.z[lane]      * bscale;
                float z1 = M.z[lane + 32] * bscale;
                float z2 = M.z[lane + 64] * bscale;
                float z3 = M.z[lane + 96] * bscale;
                float mx = fmaxf(fmaxf(z0, z1), fmaxf(z2, z3));
                #pragma unroll
                for (int off = 16; off; off >>= 1)
                    mx = fmaxf(mx, __shfl_xor_sync(0xffffffffu, mx, off));
                float e0 = __expf(z0 - mx), e1 = __expf(z1 - mx);
                float e2 = __expf(z2 - mx), e3 = __expf(z3 - mx);
                float sv = e0 + e1 + e2 + e3;
                #pragma unroll
                for (int off = 16; off; off >>= 1)
                    sv += __shfl_xor_sync(0xffffffffu, sv, off);
                float inv = 1.f / sv;
                float w0 = e0 * inv, w1 = e1 * inv, w2 = e2 * inv, w3 = e3 * inv;
                M.wsm[lane]      = w0;
                M.wsm[lane + 32] = w1;
                M.wsm[lane + 64] = w2;
                M.wsm[lane + 96] = w3;
                float sq = w0*w0 + w1*w1 + w2*w2 + w3*w3;
                #pragma unroll
                for (int off = 16; off; off >>= 1)
                    sq += __shfl_xor_sync(0xffffffffu, sq, off);
                if (lane == 0) M.scal[2] = sq;
            } else {
                int i = wrp - 1;
                #pragma unroll
                for (int j = 0; j < 3; j++) {
                    int r = 41 + i + 15 * j;
                    if (r <= 79) {
                        const float4* w4 =
                            reinterpret_cast<const float4*>(&M.pw[r * HHD]);
                        float4 a0 = w4[lane],      a1 = w4[lane + 32];
                        float4 a2 = w4[lane + 64], a3 = w4[lane + 96];
                        float acc = 0.f;
                        DOT4(acc, a0, hv0) DOT4(acc, a1, hv1)
                        DOT4(acc, a2, hv2) DOT4(acc, a3, hv3)
                        #pragma unroll
                        for (int off = 16; off; off >>= 1)
                            acc += __shfl_xor_sync(0xffffffffu, acc, off);
                        if (lane == 0) proj_epi(M, r, acc);
                    }
                }
            }
            __syncthreads();
            // ---- A/B partials over OLD memory ----
            if (tid < 320) {
                int m = tid >> 3, p = tid & 7;
                float A = 0.f, Bv = 0.f;
                #pragma unroll
                for (int n = p * 16; n < p * 16 + 16; n++) {
                    float w = M.wsm[n];
                    float mv = M.mem[n * 41 + m];
                    A  += w * mv;
                    Bv += w * w * mv;
                }
                M.rredA[tid] = A;
                M.rredB[tid] = Bv;
            }
            __syncthreads();
            // ---- r = A - e.B + s2*a  (post rflag before mem update) ----
            if (tid < MMD) {
                float A = 0.f, Bv = 0.f;
                #pragma unroll
                for (int p = 0; p < 8; p++) {
                    A  += M.rredA[tid * 8 + p];
                    Bv += M.rredB[tid * 8 + p];
                }
                g_r[hp][b][tid] = A - M.ev[tid] * Bv + M.scal[2] * M.av[tid];
            }
            __syncthreads();
            if (tid == 0) {
                __threadfence();
                st_rel(&g_rflags[cta * 32], rb0 + (unsigned)(t + 1));
            }
            // ---- memory erase/add (off critical path) ----
            if (tid < NND) {
                float wv = M.wsm[tid];
                float* mr = &M.mem[tid * 41];
                #pragma unroll
                for (int m = 0; m < MMD; m++)
                    mr[m] = mr[m] * (1.f - wv * M.ev[m]) + wv * M.av[m];
            }
        }
    } else {
        // =================== gemm CTA loop (R7 verbatim) ===================
        GemmS& G = s.u.g;
        for (int t = 0; t < TT; t++) {
            const int hp = t & 1;
            // ---- part 1: finish gates with r(t-1) -> h(t) ----
            if (t > 0) {
                if (wrp == 0) {
                    unsigned tgt = rb0 + (unsigned)t;
                    for (;;) {
                        bool ok = true;
                        if (lane < NMEM)
                            ok = ((int)(ld_acq(&g_rflags[lane * 32]) - tgt) >= 0);
                        if (__all_sync(0xffffffffu, ok)) break;
                    }
                }
                __syncthreads();
                if (tid < 160) {       // stage r(t-1) into inp f4 slots 144..153
                    int b = tid / 10, q = tid - b * 10;
                    const float4* gr4 =
                        reinterpret_cast<const float4*>(&g_r[hp ^ 1][b][0]);
                    reinterpret_cast<float4*>(G.inp)[b * KP4 + 144 + q] =
                        __ldcg(gr4 + q);
                }
                __syncthreads();
            }
            if (tid < 64) {            // r-part (40 dims) folded into red
                const int kc = tid >> 4, tile = tid & 15;
                const int rg = tile & 3, bg = tile >> 2;
                const int roff = (kc < 2) ? 144 + kc * 3 : 150 + (kc - 2) * 2;
                const int rlen = (kc < 2) ? 3 : 2;
                const float4* W4 = reinterpret_cast<const float4*>(G.W);
                const float4* I4 = reinterpret_cast<const float4*>(G.inp);
                float a[20];
                float* rb = &G.red[(kc * 16 + tile) * RWS];
                #pragma unroll
                for (int q = 0; q < 20; q++) a[q] = rb[q];
                #pragma unroll 3
                for (int q = 0; q < rlen; q++) {
                    float4 wv[5], iv[4];
                    #pragma unroll
                    for (int i = 0; i < 5; i++)
                        wv[i] = W4[(rg + 4 * i) * KP4 + roff + q];
                    #pragma unroll
                    for (int j = 0; j < 4; j++)
                        iv[j] = I4[(bg + 4 * j) * KP4 + roff + q];
                    #pragma unroll
                    for (int i = 0; i < 5; i++) {
                        #pragma unroll
                        for (int j = 0; j < 4; j++) { DOT4(a[i * 4 + j], wv[i], iv[j]) }
                    }
                }
                #pragma unroll
                for (int q = 0; q < 20; q++) rb[q] = a[q];
            }
            __syncthreads();
            if (tid < RWS * BB) {      // reduce split-K
                int b = tid / RWS, lr = tid - b * RWS;
                int tile = (b & 3) * 4 + (lr & 3);
                int cell = (lr >> 2) * 4 + (b >> 2);
                float v = G.bias[lr];
                #pragma unroll
                for (int kc2 = 0; kc2 < 32; kc2++)
                    v += G.red[(kc2 * 16 + tile) * RWS + cell];
                G.gate[lr * BB + b] = v;
            }
            __syncthreads();
            if (tid < 5 * BB) {        // LSTM pointwise -> h(t)
                int b = tid / 5, hl = tid - b * 5;
                if (hl < cnt) {
                    float gv_i = G.gate[(0 + 4 * hl) * BB + b];
                    float gv_f = G.gate[(1 + 4 * hl) * BB + b];
                    float gv_g = G.gate[(2 + 4 * hl) * BB + b];
                    float gv_o = G.gate[(3 + 4 * hl) * BB + b];
                    float iv = 1.f / (1.f + expf(-gv_i));
                    float fv = 1.f / (1.f + expf(-gv_f));
                    float gv = tanhf(gv_g);
                    float ov = 1.f / (1.f + expf(-gv_o));
                    float cn = fv * G.cst[hl * BB + b] + iv * gv;
                    float hn = ov * tanhf(cn);
                    G.cst[hl * BB + b] = cn;
                    g_h[hp][b][hbase + hl] = hn;
                    if (t == TT - 1) {
                        out_h[b * HHD + hbase + hl] = hn;
                        out_c[b * HHD + hbase + hl] = cn;
                    }
                }
            }
            __syncthreads();
            if (tid == 0) {
                __threadfence();
                st_rel(&g_hflags[gi * 32], hb0 + (unsigned)(t + 1));
            }
            // ---- window B: prestage, fc(t), xh-gemm for t+1 ----
            wait_hflags(hb0 + (unsigned)(t + 1));
            for (int idx = tid; idx < BB * 144; idx += NTHR) {
                int b = idx / 144, q = idx - b * 144;
                float4 v;
                if (q < 16) {
                    v = (t + 1 < TT)
                        ? __ldg(reinterpret_cast<const float4*>(
                              &x[(b * TT + t + 1) * IND]) + q)
                        : make_float4(0.f, 0.f, 0.f, 0.f);
                } else {
                    v = __ldcg(reinterpret_cast<const float4*>(&g_h[hp][b][0])
                               + (q - 16));
                }
                reinterpret_cast<float4*>(G.inp)[b * KP4 + q] = v;
            }
            __syncthreads();
            {   // fc(t) from staged h
                int grp = tid >> 4, l16 = tid & 15;
                int d = gi + NGEMM * grp;
                bool valid = (d < 1024);
                int d2 = valid ? d : 0;
                int b = d2 >> 6, row = d2 & 63;
                const float4* w4 =
                    reinterpret_cast<const float4*>(W_fc + row * HHD);
                const float4* h4 =
                    reinterpret_cast<const float4*>(G.inp) + b * KP4 + 16;
                float acc = 0.f;
                #pragma unroll
                for (int q = 0; q < 8; q++) {
                    float4 wv = __ldg(w4 + l16 + 16 * q);
                    float4 hv = h4[l16 + 16 * q];
                    DOT4(acc, wv, hv)
                }
                #pragma unroll
                for (int off = 8; off; off >>= 1)
                    acc += __shfl_xor_sync(0xffffffffu, acc, off);
                if (valid && l16 == 0)
                    out_O[(b * TT + t) * OUTD + row] = tanhf(acc + b_fc[row]);
            }
            if (t + 1 < TT) gemm_xh(G, tid);
        }
        if (cta == NCTA - 1 && tid == 0) {
            st_rel(&g_gen, gen + 1);   // next launch's flag base
        }
    }
}

extern "C" void kernel_launch(void* const* d_in, const int* in_sizes, int n_in,
                              void* d_out, int out_size) {
    (void)in_sizes; (void)n_in; (void)out_size;
    cudaFuncSetAttribute(ntm_kernel,
                         cudaFuncAttributeMaxDynamicSharedMemorySize,
                         (int)sizeof(Smem));
    ntm_kernel<<<NCTA, NTHR, sizeof(Smem)>>>(
        (const float*)d_in[0],  (const float*)d_in[1],  (const float*)d_in[2],
        (const float*)d_in[3],  (const float*)d_in[4],  (const float*)d_in[5],
        (const float*)d_in[6],  (const float*)d_in[7],  (const float*)d_in[8],
        (const float*)d_in[9],  (const float*)d_in[10], (const float*)d_in[11],
        (const float*)d_in[12], (const float*)d_in[13], (const float*)d_in[14],
        (const float*)d_in[15], (const float*)d_in[16], (const float*)d_in[17],
        (const float*)d_in[18], (float*)d_out);
}